// round 9
// baseline (speedup 1.0000x reference)
#include <cuda_runtime.h>
#include <math.h>
#include <stdint.h>

#define DIM   1024
#define HEADS 16
#define BSZ   2
#define SEQ   2048
#define HD    64
#define ROWS  (BSZ*SEQ)   // 4096

// Scratch (device globals; allocation-free)
__device__ float g_qkv[(size_t)ROWS * 3 * DIM];
__device__ float g_attn[(size_t)ROWS * DIM];
__device__ float g_hid[(size_t)ROWS * 2 * DIM];
// tf32-rounded copies of inputs
__device__ float g_seq_t[(size_t)ROWS * DIM];
__device__ float g_wqkv_t[(size_t)DIM * 3 * DIM];
__device__ float g_w1_t[(size_t)DIM * 2 * DIM];
__device__ float g_w2_t[(size_t)2 * DIM * DIM];

// ---------------------------------------------------------------------------
// helpers
// ---------------------------------------------------------------------------
__device__ __forceinline__ void cp16(void* smem_dst, const void* gmem_src) {
    uint32_t d = (uint32_t)__cvta_generic_to_shared(smem_dst);
    asm volatile("cp.async.cg.shared.global [%0], [%1], 16;\n" :: "r"(d), "l"(gmem_src));
}
#define CP_COMMIT() asm volatile("cp.async.commit_group;\n" ::: "memory")
#define CP_WAIT1()  asm volatile("cp.async.wait_group 1;\n" ::: "memory")

__device__ __forceinline__ float f2tf32f(float x) {
    uint32_t r;
    asm("cvt.rna.tf32.f32 %0, %1;" : "=r"(r) : "f"(x));
    return __uint_as_float(r);
}

__device__ __forceinline__ float fexp2(float x) {
    float y;
    asm("ex2.approx.ftz.f32 %0, %1;" : "=f"(y) : "f"(x));
    return y;
}

__device__ __forceinline__ void mma_tf32(float c[4], const uint32_t a[4], const uint32_t* b) {
    asm volatile(
        "mma.sync.aligned.m16n8k8.row.col.f32.tf32.tf32.f32 "
        "{%0,%1,%2,%3}, {%4,%5,%6,%7}, {%8,%9}, {%0,%1,%2,%3};\n"
        : "+f"(c[0]), "+f"(c[1]), "+f"(c[2]), "+f"(c[3])
        : "r"(a[0]), "r"(a[1]), "r"(a[2]), "r"(a[3]), "r"(b[0]), "r"(b[1]));
}

__device__ __forceinline__ void ldsm_x4(uint32_t r[4], uint32_t addr) {
    asm volatile("ldmatrix.sync.aligned.m8n8.x4.shared.b16 {%0,%1,%2,%3}, [%4];"
                 : "=r"(r[0]), "=r"(r[1]), "=r"(r[2]), "=r"(r[3]) : "r"(addr));
}

// ---------------------------------------------------------------------------
// tf32 rounding pre-pass
// ---------------------------------------------------------------------------
__global__ __launch_bounds__(256)
void cvt_tf32_kernel(const float* __restrict__ src, float* __restrict__ dst)
{
    size_t i = ((size_t)blockIdx.x * 256 + threadIdx.x) * 4;
    float4 v = *(const float4*)(src + i);
    v.x = f2tf32f(v.x); v.y = f2tf32f(v.y);
    v.z = f2tf32f(v.z); v.w = f2tf32f(v.w);
    *(float4*)(dst + i) = v;
}

// ---------------------------------------------------------------------------
// tf32 tensor-core GEMM. A via ldmatrix.x4, B via scalar LDS, with 2-deep
// register double-buffering of fragments across kq steps.
// ---------------------------------------------------------------------------
#define AS_STRIDE 36
#define BS_STRIDE 136
#define A_STAGE (128 * AS_STRIDE)
#define B_STAGE (32 * BS_STRIDE)
#define GEMM_SMEM_BYTES (3 * (A_STAGE + B_STAGE) * 4)  // 107520

__device__ __forceinline__ void gemm_load_tile(
    const float* __restrict__ A, const float* __restrict__ B,
    int K, int N, int bm, int bn, int k0,
    float* Asb, float* Bsb, int tid)
{
    #pragma unroll
    for (int i = 0; i < 4; i++) {
        int id = tid + i * 256;
        int rA = id >> 3, qA = (id & 7) * 4;
        cp16(Asb + rA * AS_STRIDE + qA, A + (size_t)(bm + rA) * K + k0 + qA);
        int rB = id >> 5, qB = (id & 31) * 4;
        cp16(Bsb + rB * BS_STRIDE + qB, B + (size_t)(k0 + rB) * N + bn + qB);
    }
}

__device__ __forceinline__ void gemm_frags(
    uint32_t a_stage, const float* Bsb, int b_col0, int tig, int kq,
    uint32_t af[4][4], uint32_t bf[4][2])
{
    const int k0s = kq * 8;
    #pragma unroll
    for (int mt = 0; mt < 4; mt++)
        ldsm_x4(af[mt], a_stage + (uint32_t)((mt * 16 * AS_STRIDE + k0s) * 4));
    #pragma unroll
    for (int nt = 0; nt < 4; nt++) {
        const float* bp = Bsb + (k0s + tig) * BS_STRIDE + b_col0 + nt * 8;
        bf[nt][0] = __float_as_uint(bp[0]);
        bf[nt][1] = __float_as_uint(bp[4 * BS_STRIDE]);
    }
}

template<int ACT, int ROUND>
__global__ __launch_bounds__(256, 2)
void tgemm_kernel(const float* __restrict__ A, const float* __restrict__ B,
                  const float* __restrict__ bias, float* __restrict__ C,
                  int M, int N, int K)
{
    extern __shared__ float smem[];
    float* As = smem;
    float* Bs = smem + 3 * A_STAGE;

    const int tid  = threadIdx.x;
    const int lane = tid & 31;
    const int wid  = tid >> 5;
    const int gid  = lane >> 2;
    const int tig  = lane & 3;
    const int warp_m = wid & 1;
    const int warp_n = wid >> 1;
    const int bm = blockIdx.y * 128;
    const int bn = blockIdx.x * 128;

    const int lf = lane >> 3, lr = lane & 7;
    const uint32_t As_u32 = (uint32_t)__cvta_generic_to_shared(As);
    const uint32_t aldm = As_u32 +
        (uint32_t)(((warp_m * 64 + (lf & 1) * 8 + lr) * AS_STRIDE + (lf >> 1) * 4) * 4);

    float acc[4][4][4];
    #pragma unroll
    for (int mt = 0; mt < 4; mt++)
        #pragma unroll
        for (int nt = 0; nt < 4; nt++)
            #pragma unroll
            for (int r = 0; r < 4; r++) acc[mt][nt][r] = 0.f;

    const int T = K / 32;
    gemm_load_tile(A, B, K, N, bm, bn, 0,  As,           Bs,           tid); CP_COMMIT();
    gemm_load_tile(A, B, K, N, bm, bn, 32, As + A_STAGE, Bs + B_STAGE, tid); CP_COMMIT();

    const int b_col0 = warp_n * 32 + gid;

    for (int t = 0; t < T; t++) {
        CP_WAIT1();
        __syncthreads();

        int tn = t + 2;
        if (tn < T) {
            gemm_load_tile(A, B, K, N, bm, bn, tn * 32,
                           As + (tn % 3) * A_STAGE, Bs + (tn % 3) * B_STAGE, tid);
        }
        CP_COMMIT();

        const uint32_t a_stage = aldm + (uint32_t)((t % 3) * A_STAGE * 4);
        const float* Bsb = Bs + (t % 3) * B_STAGE;

        uint32_t af[2][4][4], bf[2][4][2];
        gemm_frags(a_stage, Bsb, b_col0, tig, 0, af[0], bf[0]);

        #pragma unroll
        for (int kq = 0; kq < 4; kq++) {
            const int cb = kq & 1, nb = cb ^ 1;
            if (kq < 3)
                gemm_frags(a_stage, Bsb, b_col0, tig, kq + 1, af[nb], bf[nb]);
            #pragma unroll
            for (int mt = 0; mt < 4; mt++)
                #pragma unroll
                for (int nt = 0; nt < 4; nt++)
                    mma_tf32(acc[mt][nt], af[cb][mt], bf[cb][nt]);
        }
    }

    #pragma unroll
    for (int mt = 0; mt < 4; mt++) {
        const int r0 = bm + warp_m * 64 + mt * 16 + gid;
        #pragma unroll
        for (int nt = 0; nt < 4; nt++) {
            const int c0 = bn + warp_n * 32 + nt * 8 + tig * 2;
            float b0 = 0.f, b1 = 0.f;
            if (bias) { b0 = bias[c0]; b1 = bias[c0 + 1]; }
            float v0 = acc[mt][nt][0] + b0;
            float v1 = acc[mt][nt][1] + b1;
            float v2 = acc[mt][nt][2] + b0;
            float v3 = acc[mt][nt][3] + b1;
            if (ACT == 1) {
                v0 = v0 / (1.f + __expf(-v0));
                v1 = v1 / (1.f + __expf(-v1));
                v2 = v2 / (1.f + __expf(-v2));
                v3 = v3 / (1.f + __expf(-v3));
            }
            if (ROUND) {
                v0 = f2tf32f(v0); v1 = f2tf32f(v1);
                v2 = f2tf32f(v2); v3 = f2tf32f(v3);
            }
            *(float2*)(C + (size_t)r0 * N + c0)       = make_float2(v0, v1);
            *(float2*)(C + (size_t)(r0 + 8) * N + c0) = make_float2(v2, v3);
        }
    }
}

// ---------------------------------------------------------------------------
// tf32 tensor-core flash attention.
// Mask prefetched to registers before S-phase; softmax in exp2 domain with
// 2-partial tree sums; all 8 P-fragments preloaded before the PV loop.
// ---------------------------------------------------------------------------
#define ATS 68
#define KV_STAGE (2 * 64 * ATS)
#define ATTN_SMEM_FLOATS (128 * ATS + 2 * KV_STAGE)
#define ATTN_SMEM_BYTES  (ATTN_SMEM_FLOATS * 4)   // 104448

#define L2E       1.44269504f
#define SCALE_L2E (0.125f * 1.44269504f)

__device__ __forceinline__ void attn_load_kv(
    const float* kbase, const float* vbase, int kv0,
    float* Kst, float* Vst, int tid)
{
    #pragma unroll
    for (int i = 0; i < 4; i++) {
        int c = tid + i * 256;
        int r = c >> 4, q = (c & 15) * 4;
        cp16(Kst + r * ATS + q, kbase + (size_t)(kv0 + r) * (3 * DIM) + q);
        cp16(Vst + r * ATS + q, vbase + (size_t)(kv0 + r) * (3 * DIM) + q);
    }
}

__global__ __launch_bounds__(256, 2)
void attn_kernel(const float* __restrict__ qkv,
                 const float* __restrict__ mask,
                 float* __restrict__ out)
{
    extern __shared__ float smem[];
    float* Ps = smem;                 // 128 x 68 : Q staging, then P
    float* KV = smem + 128 * ATS;

    const int tid  = threadIdx.x;
    const int lane = tid & 31;
    const int w    = tid >> 5;
    const int gid  = lane >> 2;
    const int tig  = lane & 3;
    const int bb = blockIdx.z, h = blockIdx.y;
    const int q0 = blockIdx.x * 128;
    const size_t ldq = 3 * DIM;

    const float* qbase = qkv + (size_t)(bb * SEQ + q0) * ldq + h * HD;
    const float* kbase = qkv + (size_t)(bb * SEQ) * ldq + DIM + h * HD;
    const float* vbase = kbase + DIM;

    const int lf = lane >> 3, lr = lane & 7;
    const uint32_t Ps_u32 = (uint32_t)__cvta_generic_to_shared(Ps);
    const uint32_t KV_u32 = (uint32_t)__cvta_generic_to_shared(KV);
    const uint32_t pldm = Ps_u32 +
        (uint32_t)(((w * 16 + (lf & 1) * 8 + lr) * ATS + (lf >> 1) * 4) * 4);
    const uint32_t kldm_off =
        (uint32_t)((((lf >> 1) * 8 + lr) * ATS + (lf & 1) * 4) * 4);

    #pragma unroll
    for (int i = 0; i < 8; i++) {
        int c = tid + i * 256;
        int r = c >> 4, q = (c & 15) * 4;
        cp16(Ps + r * ATS + q, qbase + (size_t)r * ldq + q);
    }
    attn_load_kv(kbase, vbase, 0, KV, KV + 64 * ATS, tid);
    CP_COMMIT();

    uint32_t qf[8][4];
    float oacc[8][4];
    #pragma unroll
    for (int nt = 0; nt < 8; nt++)
        #pragma unroll
        for (int r = 0; r < 4; r++) oacc[nt][r] = 0.f;
    float mrow0 = -1e30f, mrow1 = -1e30f, lrow0 = 0.f, lrow1 = 0.f;

    const int qrow = w * 16 + gid;
    const int Rg = q0 + qrow;

    const int NT = SEQ / 64;
    for (int t = 0; t < NT; t++) {
        const int cur = t & 1;
        if (t + 1 < NT) {
            float* Kn = KV + ((t + 1) & 1) * KV_STAGE;
            attn_load_kv(kbase, vbase, (t + 1) * 64, Kn, Kn + 64 * ATS, tid);
        }
        CP_COMMIT();

        // mask prefetch (L2-latency hidden under S-phase MMAs), scaled by log2e
        const int kv0 = t * 64;
        const float* mp0 = mask + (size_t)Rg * SEQ + kv0 + 2 * tig;
        const float* mp1 = mp0 + 8 * SEQ;
        float2 mk0a[8], mk1a[8];
        #pragma unroll
        for (int nt = 0; nt < 8; nt++) {
            mk0a[nt] = *(const float2*)(mp0 + nt * 8);
            mk1a[nt] = *(const float2*)(mp1 + nt * 8);
            mk0a[nt].x *= L2E; mk0a[nt].y *= L2E;
            mk1a[nt].x *= L2E; mk1a[nt].y *= L2E;
        }

        CP_WAIT1();
        __syncthreads();

        if (t == 0) {
            #pragma unroll
            for (int kt = 0; kt < 8; kt++)
                ldsm_x4(qf[kt], pldm + (uint32_t)(kt * 8 * 4));
        }

        const uint32_t kst_u32 = KV_u32 + (uint32_t)(cur * KV_STAGE * 4) + kldm_off;
        const float* Vst = KV + cur * KV_STAGE + 64 * ATS;

        float sa[8][4];
        #pragma unroll
        for (int nt = 0; nt < 8; nt++)
            #pragma unroll
            for (int r = 0; r < 4; r++) sa[nt][r] = 0.f;

        #pragma unroll
        for (int kt = 0; kt < 8; kt++) {
            #pragma unroll
            for (int np = 0; np < 4; np++) {
                uint32_t bfr4[4];
                ldsm_x4(bfr4, kst_u32 + (uint32_t)((np * 16 * ATS + kt * 8) * 4));
                mma_tf32(sa[2 * np],     qf[kt], bfr4);
                mma_tf32(sa[2 * np + 1], qf[kt], bfr4 + 2);
            }
        }

        // scores in log2 domain: s*scale*log2e + mask*log2e
        #pragma unroll
        for (int nt = 0; nt < 8; nt++) {
            sa[nt][0] = fmaf(sa[nt][0], SCALE_L2E, mk0a[nt].x);
            sa[nt][1] = fmaf(sa[nt][1], SCALE_L2E, mk0a[nt].y);
            sa[nt][2] = fmaf(sa[nt][2], SCALE_L2E, mk1a[nt].x);
            sa[nt][3] = fmaf(sa[nt][3], SCALE_L2E, mk1a[nt].y);
        }

        float mx0 = -1e30f, mx1 = -1e30f;
        #pragma unroll
        for (int nt = 0; nt < 8; nt++) {
            mx0 = fmaxf(mx0, fmaxf(sa[nt][0], sa[nt][1]));
            mx1 = fmaxf(mx1, fmaxf(sa[nt][2], sa[nt][3]));
        }
        mx0 = fmaxf(mx0, __shfl_xor_sync(0xffffffffu, mx0, 1));
        mx0 = fmaxf(mx0, __shfl_xor_sync(0xffffffffu, mx0, 2));
        mx1 = fmaxf(mx1, __shfl_xor_sync(0xffffffffu, mx1, 1));
        mx1 = fmaxf(mx1, __shfl_xor_sync(0xffffffffu, mx1, 2));

        float mn0 = fmaxf(mrow0, mx0);
        float mn1 = fmaxf(mrow1, mx1);
        float alpha0 = fexp2(mrow0 - mn0);
        float alpha1 = fexp2(mrow1 - mn1);
        mrow0 = mn0; mrow1 = mn1;

        float s0a = 0.f, s0b = 0.f, s1a = 0.f, s1b = 0.f;
        #pragma unroll
        for (int nt = 0; nt < 8; nt++) {
            sa[nt][0] = fexp2(sa[nt][0] - mn0);
            sa[nt][1] = fexp2(sa[nt][1] - mn0);
            sa[nt][2] = fexp2(sa[nt][2] - mn1);
            sa[nt][3] = fexp2(sa[nt][3] - mn1);
            if (nt & 1) { s0b += sa[nt][0] + sa[nt][1]; s1b += sa[nt][2] + sa[nt][3]; }
            else        { s0a += sa[nt][0] + sa[nt][1]; s1a += sa[nt][2] + sa[nt][3]; }
        }
        float sum0 = s0a + s0b, sum1 = s1a + s1b;
        sum0 += __shfl_xor_sync(0xffffffffu, sum0, 1);
        sum0 += __shfl_xor_sync(0xffffffffu, sum0, 2);
        sum1 += __shfl_xor_sync(0xffffffffu, sum1, 1);
        sum1 += __shfl_xor_sync(0xffffffffu, sum1, 2);
        lrow0 = lrow0 * alpha0 + sum0;
        lrow1 = lrow1 * alpha1 + sum1;

        #pragma unroll
        for (int nt = 0; nt < 8; nt++) {
            oacc[nt][0] *= alpha0;
            oacc[nt][1] *= alpha0;
            oacc[nt][2] *= alpha1;
            oacc[nt][3] *= alpha1;
        }

        float* pr0 = Ps + qrow * ATS + 2 * tig;
        float* pr1 = pr0 + 8 * ATS;
        #pragma unroll
        for (int nt = 0; nt < 8; nt++) {
            *(float2*)(pr0 + nt * 8) = make_float2(f2tf32f(sa[nt][0]), f2tf32f(sa[nt][1]));
            *(float2*)(pr1 + nt * 8) = make_float2(f2tf32f(sa[nt][2]), f2tf32f(sa[nt][3]));
        }
        __syncwarp();

        // preload all P fragments (sa registers are dead now)
        uint32_t pf[8][4];
        #pragma unroll
        for (int kt = 0; kt < 8; kt++)
            ldsm_x4(pf[kt], pldm + (uint32_t)(kt * 8 * 4));

        #pragma unroll
        for (int kt = 0; kt < 8; kt++) {
            #pragma unroll
            for (int nt = 0; nt < 8; nt++) {
                const float* bp = Vst + (kt * 8 + tig) * ATS + nt * 8 + gid;
                uint32_t bfr[2] = { __float_as_uint(bp[0]), __float_as_uint(bp[4 * ATS]) };
                mma_tf32(oacc[nt], pf[kt], bfr);
            }
        }
        __syncthreads();
    }

    float inv0 = 1.f / lrow0, inv1 = 1.f / lrow1;
    float* o0 = out + (size_t)(bb * SEQ + Rg) * DIM + h * HD + 2 * tig;
    float* o1 = o0 + 8 * DIM;
    #pragma unroll
    for (int nt = 0; nt < 8; nt++) {
        *(float2*)(o0 + nt * 8) = make_float2(f2tf32f(oacc[nt][0] * inv0),
                                              f2tf32f(oacc[nt][1] * inv0));
        *(float2*)(o1 + nt * 8) = make_float2(f2tf32f(oacc[nt][2] * inv1),
                                              f2tf32f(oacc[nt][3] * inv1));
    }
}

// ---------------------------------------------------------------------------
// Launch
// ---------------------------------------------------------------------------
extern "C" void kernel_launch(void* const* d_in, const int* in_sizes, int n_in,
                              void* d_out, int out_size)
{
    const float* seq   = (const float*)d_in[0];
    const float* amask = (const float*)d_in[1];
    const float* Wqkv  = (const float*)d_in[2];
    const float* W1    = (const float*)d_in[3];
    const float* b1    = (const float*)d_in[4];
    const float* W2    = (const float*)d_in[5];
    const float* b2    = (const float*)d_in[6];
    float* out = (float*)d_out;

    float *qkv, *attn, *hid, *seq_t, *wqkv_t, *w1_t, *w2_t;
    cudaGetSymbolAddress((void**)&qkv,    g_qkv);
    cudaGetSymbolAddress((void**)&attn,   g_attn);
    cudaGetSymbolAddress((void**)&hid,    g_hid);
    cudaGetSymbolAddress((void**)&seq_t,  g_seq_t);
    cudaGetSymbolAddress((void**)&wqkv_t, g_wqkv_t);
    cudaGetSymbolAddress((void**)&w1_t,   g_w1_t);
    cudaGetSymbolAddress((void**)&w2_t,   g_w2_t);

    cudaFuncSetAttribute((const void*)tgemm_kernel<0,1>, cudaFuncAttributeMaxDynamicSharedMemorySize, GEMM_SMEM_BYTES);
    cudaFuncSetAttribute((const void*)tgemm_kernel<1,1>, cudaFuncAttributeMaxDynamicSharedMemorySize, GEMM_SMEM_BYTES);
    cudaFuncSetAttribute((const void*)tgemm_kernel<0,0>, cudaFuncAttributeMaxDynamicSharedMemorySize, GEMM_SMEM_BYTES);
    cudaFuncSetAttribute((const void*)attn_kernel,       cudaFuncAttributeMaxDynamicSharedMemorySize, ATTN_SMEM_BYTES);

    // 0) tf32 pre-rounding of inputs
    cvt_tf32_kernel<<<(ROWS * DIM) / 1024, 256>>>(seq, seq_t);
    cvt_tf32_kernel<<<(DIM * 3 * DIM) / 1024, 256>>>(Wqkv, wqkv_t);
    cvt_tf32_kernel<<<(DIM * 2 * DIM) / 1024, 256>>>(W1, w1_t);
    cvt_tf32_kernel<<<(2 * DIM * DIM) / 1024, 256>>>(W2, w2_t);

    // 1) QKV projection (output rounded: feeds attention)
    {
        dim3 grid(3 * DIM / 128, ROWS / 128);
        tgemm_kernel<0,1><<<grid, 256, GEMM_SMEM_BYTES>>>(seq_t, wqkv_t, nullptr, qkv, ROWS, 3 * DIM, DIM);
    }
    // 2) Attention (output rounded: feeds FFN1)
    {
        dim3 grid(SEQ / 128, HEADS, BSZ);
        attn_kernel<<<grid, 256, ATTN_SMEM_BYTES>>>(qkv, amask, attn);
    }
    // 3) FFN1 + bias + SiLU (output rounded: feeds FFN2)
    {
        dim3 grid(2 * DIM / 128, ROWS / 128);
        tgemm_kernel<1,1><<<grid, 256, GEMM_SMEM_BYTES>>>(attn, w1_t, b1, hid, ROWS, 2 * DIM, DIM);
    }
    // 4) FFN2 + bias (final output: full fp32)
    {
        dim3 grid(DIM / 128, ROWS / 128);
        tgemm_kernel<0,0><<<grid, 256, GEMM_SMEM_BYTES>>>(hid, w2_t, b2, out, ROWS, DIM, 2 * DIM);
    }
}

// round 10
// speedup vs baseline: 1.0388x; 1.0388x over previous
#include <cuda_runtime.h>
#include <math.h>
#include <stdint.h>

#define DIM   1024
#define HEADS 16
#define BSZ   2
#define SEQ   2048
#define HD    64
#define ROWS  (BSZ*SEQ)   // 4096

// Scratch (device globals; allocation-free)
__device__ float g_qkv[(size_t)ROWS * 3 * DIM];
__device__ float g_attn[(size_t)ROWS * DIM];
__device__ float g_hid[(size_t)ROWS * 2 * DIM];
// tf32-rounded copies of inputs
__device__ float g_seq_t[(size_t)ROWS * DIM];
__device__ float g_wqkv_t[(size_t)DIM * 3 * DIM];
__device__ float g_w1_t[(size_t)DIM * 2 * DIM];
__device__ float g_w2_t[(size_t)2 * DIM * DIM];

// ---------------------------------------------------------------------------
// helpers
// ---------------------------------------------------------------------------
__device__ __forceinline__ void cp16(void* smem_dst, const void* gmem_src) {
    uint32_t d = (uint32_t)__cvta_generic_to_shared(smem_dst);
    asm volatile("cp.async.cg.shared.global [%0], [%1], 16;\n" :: "r"(d), "l"(gmem_src));
}
#define CP_COMMIT() asm volatile("cp.async.commit_group;\n" ::: "memory")
#define CP_WAIT1()  asm volatile("cp.async.wait_group 1;\n" ::: "memory")

__device__ __forceinline__ float f2tf32f(float x) {
    uint32_t r;
    asm("cvt.rna.tf32.f32 %0, %1;" : "=r"(r) : "f"(x));
    return __uint_as_float(r);
}

__device__ __forceinline__ float fexp2(float x) {
    float y;
    asm("ex2.approx.ftz.f32 %0, %1;" : "=f"(y) : "f"(x));
    return y;
}

__device__ __forceinline__ void mma_tf32(float c[4], const uint32_t a[4], const uint32_t* b) {
    asm volatile(
        "mma.sync.aligned.m16n8k8.row.col.f32.tf32.tf32.f32 "
        "{%0,%1,%2,%3}, {%4,%5,%6,%7}, {%8,%9}, {%0,%1,%2,%3};\n"
        : "+f"(c[0]), "+f"(c[1]), "+f"(c[2]), "+f"(c[3])
        : "r"(a[0]), "r"(a[1]), "r"(a[2]), "r"(a[3]), "r"(b[0]), "r"(b[1]));
}

__device__ __forceinline__ void ldsm_x4(uint32_t r[4], uint32_t addr) {
    asm volatile("ldmatrix.sync.aligned.m8n8.x4.shared.b16 {%0,%1,%2,%3}, [%4];"
                 : "=r"(r[0]), "=r"(r[1]), "=r"(r[2]), "=r"(r[3]) : "r"(addr));
}

// ---------------------------------------------------------------------------
// fused tf32 rounding pre-pass: one launch covers all four arrays.
// Each block converts 1024 elements (256 threads x float4).
// Block ranges: [0,4096) seq, [4096,7168) Wqkv, [7168,9216) W1, [9216,11264) W2
// ---------------------------------------------------------------------------
#define CVT_BLOCKS 11264

__global__ __launch_bounds__(256)
void cvt_all_kernel(const float* __restrict__ s0, float* __restrict__ d0,
                    const float* __restrict__ s1, float* __restrict__ d1,
                    const float* __restrict__ s2, float* __restrict__ d2,
                    const float* __restrict__ s3, float* __restrict__ d3)
{
    int b = blockIdx.x;
    const float* src;
    float* dst;
    size_t base;
    if (b < 4096)      { src = s0; dst = d0; base = (size_t)b * 1024; }
    else if (b < 7168) { src = s1; dst = d1; base = (size_t)(b - 4096) * 1024; }
    else if (b < 9216) { src = s2; dst = d2; base = (size_t)(b - 7168) * 1024; }
    else               { src = s3; dst = d3; base = (size_t)(b - 9216) * 1024; }
    size_t i = base + (size_t)threadIdx.x * 4;
    float4 v = *(const float4*)(src + i);
    v.x = f2tf32f(v.x); v.y = f2tf32f(v.y);
    v.z = f2tf32f(v.z); v.w = f2tf32f(v.w);
    *(float4*)(dst + i) = v;
}

// ---------------------------------------------------------------------------
// tf32 tensor-core GEMM (R8 form). A via ldmatrix.x4; B via scalar LDS.
// ---------------------------------------------------------------------------
#define AS_STRIDE 36
#define BS_STRIDE 136
#define A_STAGE (128 * AS_STRIDE)
#define B_STAGE (32 * BS_STRIDE)
#define GEMM_SMEM_BYTES (3 * (A_STAGE + B_STAGE) * 4)  // 107520

__device__ __forceinline__ void gemm_load_tile(
    const float* __restrict__ A, const float* __restrict__ B,
    int K, int N, int bm, int bn, int k0,
    float* Asb, float* Bsb, int tid)
{
    #pragma unroll
    for (int i = 0; i < 4; i++) {
        int id = tid + i * 256;
        int rA = id >> 3, qA = (id & 7) * 4;
        cp16(Asb + rA * AS_STRIDE + qA, A + (size_t)(bm + rA) * K + k0 + qA);
        int rB = id >> 5, qB = (id & 31) * 4;
        cp16(Bsb + rB * BS_STRIDE + qB, B + (size_t)(k0 + rB) * N + bn + qB);
    }
}

template<int ACT, int ROUND>
__global__ __launch_bounds__(256, 2)
void tgemm_kernel(const float* __restrict__ A, const float* __restrict__ B,
                  const float* __restrict__ bias, float* __restrict__ C,
                  int M, int N, int K)
{
    extern __shared__ float smem[];
    float* As = smem;
    float* Bs = smem + 3 * A_STAGE;

    const int tid  = threadIdx.x;
    const int lane = tid & 31;
    const int wid  = tid >> 5;
    const int gid  = lane >> 2;
    const int tig  = lane & 3;
    const int warp_m = wid & 1;
    const int warp_n = wid >> 1;
    const int bm = blockIdx.y * 128;
    const int bn = blockIdx.x * 128;

    const int lf = lane >> 3, lr = lane & 7;
    const uint32_t As_u32 = (uint32_t)__cvta_generic_to_shared(As);
    const uint32_t aldm = As_u32 +
        (uint32_t)(((warp_m * 64 + (lf & 1) * 8 + lr) * AS_STRIDE + (lf >> 1) * 4) * 4);

    float acc[4][4][4];
    #pragma unroll
    for (int mt = 0; mt < 4; mt++)
        #pragma unroll
        for (int nt = 0; nt < 4; nt++)
            #pragma unroll
            for (int r = 0; r < 4; r++) acc[mt][nt][r] = 0.f;

    const int T = K / 32;
    gemm_load_tile(A, B, K, N, bm, bn, 0,  As,           Bs,           tid); CP_COMMIT();
    gemm_load_tile(A, B, K, N, bm, bn, 32, As + A_STAGE, Bs + B_STAGE, tid); CP_COMMIT();

    const int b_col0 = warp_n * 32 + gid;

    for (int t = 0; t < T; t++) {
        CP_WAIT1();
        __syncthreads();

        int tn = t + 2;
        if (tn < T) {
            gemm_load_tile(A, B, K, N, bm, bn, tn * 32,
                           As + (tn % 3) * A_STAGE, Bs + (tn % 3) * B_STAGE, tid);
        }
        CP_COMMIT();

        const uint32_t a_stage = aldm + (uint32_t)((t % 3) * A_STAGE * 4);
        const float* Bsb = Bs + (t % 3) * B_STAGE;

        #pragma unroll
        for (int kq = 0; kq < 4; kq++) {
            const int k0s = kq * 8;
            uint32_t af[4][4];
            #pragma unroll
            for (int mt = 0; mt < 4; mt++)
                ldsm_x4(af[mt], a_stage + (uint32_t)((mt * 16 * AS_STRIDE + k0s) * 4));

            uint32_t bf[4][2];
            #pragma unroll
            for (int nt = 0; nt < 4; nt++) {
                const float* bp = Bsb + (k0s + tig) * BS_STRIDE + b_col0 + nt * 8;
                bf[nt][0] = __float_as_uint(bp[0]);
                bf[nt][1] = __float_as_uint(bp[4 * BS_STRIDE]);
            }
            #pragma unroll
            for (int mt = 0; mt < 4; mt++)
                #pragma unroll
                for (int nt = 0; nt < 4; nt++)
                    mma_tf32(acc[mt][nt], af[mt], bf[nt]);
        }
    }

    #pragma unroll
    for (int mt = 0; mt < 4; mt++) {
        const int r0 = bm + warp_m * 64 + mt * 16 + gid;
        #pragma unroll
        for (int nt = 0; nt < 4; nt++) {
            const int c0 = bn + warp_n * 32 + nt * 8 + tig * 2;
            float b0 = 0.f, b1 = 0.f;
            if (bias) { b0 = bias[c0]; b1 = bias[c0 + 1]; }
            float v0 = acc[mt][nt][0] + b0;
            float v1 = acc[mt][nt][1] + b1;
            float v2 = acc[mt][nt][2] + b0;
            float v3 = acc[mt][nt][3] + b1;
            if (ACT == 1) {
                v0 = v0 / (1.f + __expf(-v0));
                v1 = v1 / (1.f + __expf(-v1));
                v2 = v2 / (1.f + __expf(-v2));
                v3 = v3 / (1.f + __expf(-v3));
            }
            if (ROUND) {
                v0 = f2tf32f(v0); v1 = f2tf32f(v1);
                v2 = f2tf32f(v2); v3 = f2tf32f(v3);
            }
            *(float2*)(C + (size_t)r0 * N + c0)       = make_float2(v0, v1);
            *(float2*)(C + (size_t)(r0 + 8) * N + c0) = make_float2(v2, v3);
        }
    }
}

// ---------------------------------------------------------------------------
// tf32 tensor-core flash attention (R8 structure) + exp2-domain softmax.
// ---------------------------------------------------------------------------
#define ATS 68
#define KV_STAGE (2 * 64 * ATS)
#define ATTN_SMEM_FLOATS (128 * ATS + 2 * KV_STAGE)
#define ATTN_SMEM_BYTES  (ATTN_SMEM_FLOATS * 4)   // 104448

#define L2E       1.44269504f
#define SCALE_L2E (0.125f * 1.44269504f)

__device__ __forceinline__ void attn_load_kv(
    const float* kbase, const float* vbase, int kv0,
    float* Kst, float* Vst, int tid)
{
    #pragma unroll
    for (int i = 0; i < 4; i++) {
        int c = tid + i * 256;
        int r = c >> 4, q = (c & 15) * 4;
        cp16(Kst + r * ATS + q, kbase + (size_t)(kv0 + r) * (3 * DIM) + q);
        cp16(Vst + r * ATS + q, vbase + (size_t)(kv0 + r) * (3 * DIM) + q);
    }
}

__global__ __launch_bounds__(256, 2)
void attn_kernel(const float* __restrict__ qkv,
                 const float* __restrict__ mask,
                 float* __restrict__ out)
{
    extern __shared__ float smem[];
    float* Ps = smem;                 // 128 x 68 : Q staging, then P
    float* KV = smem + 128 * ATS;

    const int tid  = threadIdx.x;
    const int lane = tid & 31;
    const int w    = tid >> 5;
    const int gid  = lane >> 2;
    const int tig  = lane & 3;
    const int bb = blockIdx.z, h = blockIdx.y;
    const int q0 = blockIdx.x * 128;
    const size_t ldq = 3 * DIM;

    const float* qbase = qkv + (size_t)(bb * SEQ + q0) * ldq + h * HD;
    const float* kbase = qkv + (size_t)(bb * SEQ) * ldq + DIM + h * HD;
    const float* vbase = kbase + DIM;

    const int lf = lane >> 3, lr = lane & 7;
    const uint32_t Ps_u32 = (uint32_t)__cvta_generic_to_shared(Ps);
    const uint32_t KV_u32 = (uint32_t)__cvta_generic_to_shared(KV);
    const uint32_t pldm = Ps_u32 +
        (uint32_t)(((w * 16 + (lf & 1) * 8 + lr) * ATS + (lf >> 1) * 4) * 4);
    const uint32_t kldm_off =
        (uint32_t)((((lf >> 1) * 8 + lr) * ATS + (lf & 1) * 4) * 4);

    #pragma unroll
    for (int i = 0; i < 8; i++) {
        int c = tid + i * 256;
        int r = c >> 4, q = (c & 15) * 4;
        cp16(Ps + r * ATS + q, qbase + (size_t)r * ldq + q);
    }
    attn_load_kv(kbase, vbase, 0, KV, KV + 64 * ATS, tid);
    CP_COMMIT();

    uint32_t qf[8][4];
    float oacc[8][4];
    #pragma unroll
    for (int nt = 0; nt < 8; nt++)
        #pragma unroll
        for (int r = 0; r < 4; r++) oacc[nt][r] = 0.f;
    float mrow0 = -1e30f, mrow1 = -1e30f, lrow0 = 0.f, lrow1 = 0.f;

    const int qrow = w * 16 + gid;
    const int Rg = q0 + qrow;

    const int NT = SEQ / 64;
    for (int t = 0; t < NT; t++) {
        const int cur = t & 1;
        if (t + 1 < NT) {
            float* Kn = KV + ((t + 1) & 1) * KV_STAGE;
            attn_load_kv(kbase, vbase, (t + 1) * 64, Kn, Kn + 64 * ATS, tid);
        }
        CP_COMMIT();
        CP_WAIT1();
        __syncthreads();

        if (t == 0) {
            #pragma unroll
            for (int kt = 0; kt < 8; kt++)
                ldsm_x4(qf[kt], pldm + (uint32_t)(kt * 8 * 4));
        }

        const uint32_t kst_u32 = KV_u32 + (uint32_t)(cur * KV_STAGE * 4) + kldm_off;
        const float* Vst = KV + cur * KV_STAGE + 64 * ATS;
        const int kv0 = t * 64;

        float sa[8][4];
        #pragma unroll
        for (int nt = 0; nt < 8; nt++)
            #pragma unroll
            for (int r = 0; r < 4; r++) sa[nt][r] = 0.f;

        // S = Q K^T : K-fragments via x4 ldmatrix, two n-tiles per load
        #pragma unroll
        for (int kt = 0; kt < 8; kt++) {
            #pragma unroll
            for (int np = 0; np < 4; np++) {
                uint32_t bfr4[4];
                ldsm_x4(bfr4, kst_u32 + (uint32_t)((np * 16 * ATS + kt * 8) * 4));
                mma_tf32(sa[2 * np],     qf[kt], bfr4);
                mma_tf32(sa[2 * np + 1], qf[kt], bfr4 + 2);
            }
        }

        // scale + mask, log2 domain
        const float* mp0 = mask + (size_t)Rg * SEQ + kv0 + 2 * tig;
        const float* mp1 = mp0 + 8 * SEQ;
        #pragma unroll
        for (int nt = 0; nt < 8; nt++) {
            float2 mk0 = *(const float2*)(mp0 + nt * 8);
            float2 mk1 = *(const float2*)(mp1 + nt * 8);
            sa[nt][0] = fmaf(sa[nt][0], SCALE_L2E, mk0.x * L2E);
            sa[nt][1] = fmaf(sa[nt][1], SCALE_L2E, mk0.y * L2E);
            sa[nt][2] = fmaf(sa[nt][2], SCALE_L2E, mk1.x * L2E);
            sa[nt][3] = fmaf(sa[nt][3], SCALE_L2E, mk1.y * L2E);
        }

        float mx0 = -1e30f, mx1 = -1e30f;
        #pragma unroll
        for (int nt = 0; nt < 8; nt++) {
            mx0 = fmaxf(mx0, fmaxf(sa[nt][0], sa[nt][1]));
            mx1 = fmaxf(mx1, fmaxf(sa[nt][2], sa[nt][3]));
        }
        mx0 = fmaxf(mx0, __shfl_xor_sync(0xffffffffu, mx0, 1));
        mx0 = fmaxf(mx0, __shfl_xor_sync(0xffffffffu, mx0, 2));
        mx1 = fmaxf(mx1, __shfl_xor_sync(0xffffffffu, mx1, 1));
        mx1 = fmaxf(mx1, __shfl_xor_sync(0xffffffffu, mx1, 2));

        float mn0 = fmaxf(mrow0, mx0);
        float mn1 = fmaxf(mrow1, mx1);
        float alpha0 = fexp2(mrow0 - mn0);
        float alpha1 = fexp2(mrow1 - mn1);
        mrow0 = mn0; mrow1 = mn1;

        float s0a = 0.f, s0b = 0.f, s1a = 0.f, s1b = 0.f;
        #pragma unroll
        for (int nt = 0; nt < 8; nt++) {
            sa[nt][0] = fexp2(sa[nt][0] - mn0);
            sa[nt][1] = fexp2(sa[nt][1] - mn0);
            sa[nt][2] = fexp2(sa[nt][2] - mn1);
            sa[nt][3] = fexp2(sa[nt][3] - mn1);
            if (nt & 1) { s0b += sa[nt][0] + sa[nt][1]; s1b += sa[nt][2] + sa[nt][3]; }
            else        { s0a += sa[nt][0] + sa[nt][1]; s1a += sa[nt][2] + sa[nt][3]; }
        }
        float sum0 = s0a + s0b, sum1 = s1a + s1b;
        sum0 += __shfl_xor_sync(0xffffffffu, sum0, 1);
        sum0 += __shfl_xor_sync(0xffffffffu, sum0, 2);
        sum1 += __shfl_xor_sync(0xffffffffu, sum1, 1);
        sum1 += __shfl_xor_sync(0xffffffffu, sum1, 2);
        lrow0 = lrow0 * alpha0 + sum0;
        lrow1 = lrow1 * alpha1 + sum1;

        #pragma unroll
        for (int nt = 0; nt < 8; nt++) {
            oacc[nt][0] *= alpha0;
            oacc[nt][1] *= alpha0;
            oacc[nt][2] *= alpha1;
            oacc[nt][3] *= alpha1;
        }

        float* pr0 = Ps + qrow * ATS + 2 * tig;
        float* pr1 = pr0 + 8 * ATS;
        #pragma unroll
        for (int nt = 0; nt < 8; nt++) {
            *(float2*)(pr0 + nt * 8) = make_float2(f2tf32f(sa[nt][0]), f2tf32f(sa[nt][1]));
            *(float2*)(pr1 + nt * 8) = make_float2(f2tf32f(sa[nt][2]), f2tf32f(sa[nt][3]));
        }
        __syncwarp();

        #pragma unroll
        for (int kt = 0; kt < 8; kt++) {
            uint32_t pf[4];
            ldsm_x4(pf, pldm + (uint32_t)(kt * 8 * 4));
            #pragma unroll
            for (int nt = 0; nt < 8; nt++) {
                const float* bp = Vst + (kt * 8 + tig) * ATS + nt * 8 + gid;
                uint32_t bfr[2] = { __float_as_uint(bp[0]), __float_as_uint(bp[4 * ATS]) };
                mma_tf32(oacc[nt], pf, bfr);
            }
        }
        __syncthreads();
    }

    float inv0 = 1.f / lrow0, inv1 = 1.f / lrow1;
    float* o0 = out + (size_t)(bb * SEQ + Rg) * DIM + h * HD + 2 * tig;
    float* o1 = o0 + 8 * DIM;
    #pragma unroll
    for (int nt = 0; nt < 8; nt++) {
        *(float2*)(o0 + nt * 8) = make_float2(f2tf32f(oacc[nt][0] * inv0),
                                              f2tf32f(oacc[nt][1] * inv0));
        *(float2*)(o1 + nt * 8) = make_float2(f2tf32f(oacc[nt][2] * inv1),
                                              f2tf32f(oacc[nt][3] * inv1));
    }
}

// ---------------------------------------------------------------------------
// Launch
// ---------------------------------------------------------------------------
extern "C" void kernel_launch(void* const* d_in, const int* in_sizes, int n_in,
                              void* d_out, int out_size)
{
    const float* seq   = (const float*)d_in[0];
    const float* amask = (const float*)d_in[1];
    const float* Wqkv  = (const float*)d_in[2];
    const float* W1    = (const float*)d_in[3];
    const float* b1    = (const float*)d_in[4];
    const float* W2    = (const float*)d_in[5];
    const float* b2    = (const float*)d_in[6];
    float* out = (float*)d_out;

    float *qkv, *attn, *hid, *seq_t, *wqkv_t, *w1_t, *w2_t;
    cudaGetSymbolAddress((void**)&qkv,    g_qkv);
    cudaGetSymbolAddress((void**)&attn,   g_attn);
    cudaGetSymbolAddress((void**)&hid,    g_hid);
    cudaGetSymbolAddress((void**)&seq_t,  g_seq_t);
    cudaGetSymbolAddress((void**)&wqkv_t, g_wqkv_t);
    cudaGetSymbolAddress((void**)&w1_t,   g_w1_t);
    cudaGetSymbolAddress((void**)&w2_t,   g_w2_t);

    cudaFuncSetAttribute((const void*)tgemm_kernel<0,1>, cudaFuncAttributeMaxDynamicSharedMemorySize, GEMM_SMEM_BYTES);
    cudaFuncSetAttribute((const void*)tgemm_kernel<1,1>, cudaFuncAttributeMaxDynamicSharedMemorySize, GEMM_SMEM_BYTES);
    cudaFuncSetAttribute((const void*)tgemm_kernel<0,0>, cudaFuncAttributeMaxDynamicSharedMemorySize, GEMM_SMEM_BYTES);
    cudaFuncSetAttribute((const void*)attn_kernel,       cudaFuncAttributeMaxDynamicSharedMemorySize, ATTN_SMEM_BYTES);

    // 0) fused tf32 pre-rounding of all inputs (one launch)
    cvt_all_kernel<<<CVT_BLOCKS, 256>>>(seq, seq_t, Wqkv, wqkv_t, W1, w1_t, W2, w2_t);

    // 1) QKV projection (output rounded: feeds attention)
    {
        dim3 grid(3 * DIM / 128, ROWS / 128);
        tgemm_kernel<0,1><<<grid, 256, GEMM_SMEM_BYTES>>>(seq_t, wqkv_t, nullptr, qkv, ROWS, 3 * DIM, DIM);
    }
    // 2) Attention (output rounded: feeds FFN1)
    {
        dim3 grid(SEQ / 128, HEADS, BSZ);
        attn_kernel<<<grid, 256, ATTN_SMEM_BYTES>>>(qkv, amask, attn);
    }
    // 3) FFN1 + bias + SiLU (output rounded: feeds FFN2)
    {
        dim3 grid(2 * DIM / 128, ROWS / 128);
        tgemm_kernel<1,1><<<grid, 256, GEMM_SMEM_BYTES>>>(attn, w1_t, b1, hid, ROWS, 2 * DIM, DIM);
    }
    // 4) FFN2 + bias (final output: full fp32)
    {
        dim3 grid(DIM / 128, ROWS / 128);
        tgemm_kernel<0,0><<<grid, 256, GEMM_SMEM_BYTES>>>(hid, w2_t, b2, out, ROWS, DIM, 2 * DIM);
    }
}